// round 11
// baseline (speedup 1.0000x reference)
#include <cuda_runtime.h>
#include <cuda_fp16.h>
#include <math.h>
#include <stdint.h>

// Problem constants
#define B_   256
#define N_   32768
#define M_   64
#define R_   4
#define U_   256
#define DIN_ 512
#define G4_  1024
#define QT_  1024      // total queries = R*B
#define NSPL 32        // flash reads: split of N (1024 keys per chunk)
#define KSPL 8         // gates GEMM split-K parts

// ---------------- static scratch ----------------
__device__ float  g_gpart[KSPL * B_ * G4_];   // gates split-K partials (8 MB)
__device__ float  g_kt   [QT_ * M_];          // raw tanh keys fp32 (scatter)
__device__ __half g_ktsh [QT_ * M_];          // normalized keys * log2e, fp16 [q][m]
__device__ __half g_ktTh [R_ * M_ * B_];      // alpha-scaled keys fp16 [r][m][b]
__device__ float  g_alpha[B_ * R_];
__device__ int    g_least[B_];
__device__ float  g_pminv[B_ * 4];            // argmin chunk partial values
__device__ int    g_pmini[B_ * 4];            // argmin chunk partial indices
__device__ __half g_Ash  [N_ * M_];           // A rows / ||A[n]|| fp16 [n][m]
__device__ __half g_dA   [R_ * M_ * N_];      // write deltas fp16 [r][m][n]
__device__ float  g_emask[N_];
__device__ __half g_AnT  [M_ * N_];           // new memory fp16 [m][n]
__device__ float  g_pden [QT_ * NSPL];
__device__ float  g_pacc [QT_ * NSPL * M_];

// fast transcendentals
__device__ __forceinline__ float fsigmoid(float x) {
    return __fdividef(1.0f, 1.0f + __expf(-x));
}
__device__ __forceinline__ float ftanh(float x) {
    float e = __expf(2.0f * x);
    return __fdividef(e - 1.0f, e + 1.0f);
}
__device__ __forceinline__ float htanh(float x) {     // MUFU.TANH, 1 op
    float y;
    asm("tanh.approx.f32 %0, %1;" : "=f"(y) : "f"(x));
    return y;
}

__device__ __forceinline__ uint32_t smem_u32(const void* p) {
    uint32_t a;
    asm("{ .reg .u64 t; cvta.to.shared.u64 t, %1; cvt.u32.u64 %0, t; }" : "=r"(a) : "l"(p));
    return a;
}
__device__ __forceinline__ void ldsm4(uint32_t* r, uint32_t addr) {
    asm volatile("ldmatrix.sync.aligned.m8n8.x4.shared.b16 {%0,%1,%2,%3}, [%4];"
        : "=r"(r[0]), "=r"(r[1]), "=r"(r[2]), "=r"(r[3]) : "r"(addr));
}
__device__ __forceinline__ void ldsm4t(uint32_t* r, uint32_t addr) {
    asm volatile("ldmatrix.sync.aligned.m8n8.x4.trans.shared.b16 {%0,%1,%2,%3}, [%4];"
        : "=r"(r[0]), "=r"(r[1]), "=r"(r[2]), "=r"(r[3]) : "r"(addr));
}
__device__ __forceinline__ void mma16816(float* c, const uint32_t* a, uint32_t b0, uint32_t b1) {
    asm volatile("mma.sync.aligned.m16n8k16.row.col.f32.f16.f16.f32 "
        "{%0,%1,%2,%3}, {%4,%5,%6,%7}, {%8,%9}, {%0,%1,%2,%3};"
        : "+f"(c[0]), "+f"(c[1]), "+f"(c[2]), "+f"(c[3])
        : "r"(a[0]), "r"(a[1]), "r"(a[2]), "r"(a[3]), "r"(b0), "r"(b1));
}
__device__ __forceinline__ uint32_t packh2(float a, float b) {
    __half2 h = __floats2half2_rn(a, b);
    return *(uint32_t*)&h;
}
__device__ __forceinline__ void cpa16(uint32_t dst, const void* src) {
    asm volatile("cp.async.ca.shared.global [%0], [%1], 16;" :: "r"(dst), "l"(src));
}
#define CP_COMMIT() asm volatile("cp.async.commit_group;" ::: "memory")
#define CP_WAIT(n)  asm volatile("cp.async.wait_group %0;" :: "n"(n) : "memory")

// ---------------- K1: gates GEMM on tensor cores, split-K ----------------
__global__ void __launch_bounds__(256) k_gates_mma(
        const float* __restrict__ x, const float* __restrict__ rp,
        const float* __restrict__ h, const float* __restrict__ W,
        const float* __restrict__ Uw) {
    __shared__ __align__(16) __half sIn[128 * 24];   // [row 128][k 16 +8]
    __shared__ __align__(16) __half sW [16 * 136];   // [k 16][col 128 +8]
    const int t = threadIdx.x, w = t >> 5, l = t & 31;
    const int j0 = blockIdx.x * 128, b0 = blockIdx.y * 128, z = blockIdx.z;
    uint32_t ib = smem_u32(sIn), wb = smem_u32(sW);

    const int irow = t >> 1,  icol = (t & 1) * 8;
    const int wrow = t >> 4,  wcol = (t & 15) * 8;

    float4 iv0, iv1, wv0, wv1;
    auto ld_in = [&](int k0) {
        const float* s;
        if (k0 < DIN_)      s = x + (size_t)(b0 + irow) * DIN_ + k0 + icol;
        else if (k0 < 768) { int i0 = k0 - DIN_;
                            s = rp + ((size_t)(i0 >> 6) * B_ + b0 + irow) * M_ + (i0 & 63) + icol; }
        else                s = h + (size_t)(b0 + irow) * U_ + (k0 - 768) + icol;
        iv0 = *(const float4*)s; iv1 = *(const float4*)(s + 4);
    };
    auto ld_w = [&](int k0) {
        int kk = k0 + wrow;
        const float* s = (kk < 768) ? W + (size_t)kk * G4_ + j0 + wcol
                                    : Uw + (size_t)(kk - 768) * G4_ + j0 + wcol;
        wv0 = *(const float4*)s; wv1 = *(const float4*)(s + 4);
    };

    const int kt0 = z * (64 / KSPL);
    ld_in(kt0 * 16); ld_w(kt0 * 16);
    float acc[16][4] = {};
    for (int kt = 0; kt < 64 / KSPL; kt++) {
        __syncthreads();
        {
            uint4 o;
            o.x = packh2(iv0.x, iv0.y); o.y = packh2(iv0.z, iv0.w);
            o.z = packh2(iv1.x, iv1.y); o.w = packh2(iv1.z, iv1.w);
            *(uint4*)(sIn + irow * 24 + icol) = o;
            o.x = packh2(wv0.x, wv0.y); o.y = packh2(wv0.z, wv0.w);
            o.z = packh2(wv1.x, wv1.y); o.w = packh2(wv1.z, wv1.w);
            *(uint4*)(sW + wrow * 136 + wcol) = o;
        }
        __syncthreads();
        if (kt < 64 / KSPL - 1) { ld_in((kt0 + kt + 1) * 16); ld_w((kt0 + kt + 1) * 16); }
        uint32_t a[4];
        ldsm4(a, ib + ((w * 16 + (l & 15)) * 24 + (l >> 4) * 8) * 2);
        #pragma unroll
        for (int j = 0; j < 8; j++) {
            uint32_t bb[4];
            int rowb = (l & 7) + ((l >> 3) & 1) * 8;
            int colb = j * 16 + ((l >> 4) & 1) * 8;
            ldsm4t(bb, wb + (rowb * 136 + colb) * 2);
            mma16816(acc[2 * j],     a, bb[0], bb[1]);
            mma16816(acc[2 * j + 1], a, bb[2], bb[3]);
        }
    }
    int mr = w * 16 + (l >> 2);
    float* gp = g_gpart + (size_t)z * B_ * G4_;
    int row0 = b0 + mr, row1 = row0 + 8;
    #pragma unroll
    for (int i = 0; i < 16; i++) {
        int col = j0 + i * 8 + (l & 3) * 2;
        *(float2*)(gp + (size_t)row0 * G4_ + col) = make_float2(acc[i][0], acc[i][1]);
        *(float2*)(gp + (size_t)row1 * G4_ + col) = make_float2(acc[i][2], acc[i][3]);
    }
}

// ---------------- K2: fused LSTM + alpha + keys (block = one batch row) ----------------
__global__ void __launch_bounds__(256) k_lstm_kt(
        const float* __restrict__ c, float* __restrict__ out,
        const float* __restrict__ Wa, const float* __restrict__ ba,
        const float* __restrict__ Wk, const float* __restrict__ bk,
        const float* __restrict__ bias) {
    __shared__ float hs[256];
    __shared__ float red[8][4];
    __shared__ float sal[4];
    __shared__ float sred[8];
    const int b = blockIdx.x, u = threadIdx.x;
    const int idx = b * 256 + u;
    float gi = bias[u], gf = bias[256 + u], gg = bias[512 + u], go = bias[768 + u];
    #pragma unroll
    for (int p = 0; p < KSPL; p++) {
        const float* gp = g_gpart + (size_t)p * B_ * G4_ + (size_t)b * G4_;
        gi += gp[u]; gf += gp[256 + u]; gg += gp[512 + u]; go += gp[768 + u];
    }
    float cn = fsigmoid(gf) * c[idx] + fsigmoid(gi) * ftanh(gg);
    float hn = fsigmoid(go) * ftanh(cn);
    hs[u] = hn;
    out[b * 512 + u] = hn;
    // alpha partials
    float4 w4 = *(const float4*)(Wa + u * 4);
    float p0 = hn * w4.x, p1 = hn * w4.y, p2 = hn * w4.z, p3 = hn * w4.w;
    #pragma unroll
    for (int o = 16; o > 0; o >>= 1) {
        p0 += __shfl_xor_sync(0xffffffffu, p0, o);
        p1 += __shfl_xor_sync(0xffffffffu, p1, o);
        p2 += __shfl_xor_sync(0xffffffffu, p2, o);
        p3 += __shfl_xor_sync(0xffffffffu, p3, o);
    }
    if ((u & 31) == 0) {
        red[u >> 5][0] = p0; red[u >> 5][1] = p1;
        red[u >> 5][2] = p2; red[u >> 5][3] = p3;
    }
    __syncthreads();
    if (u < 4) {
        float a = ba[u];
        #pragma unroll
        for (int i = 0; i < 8; i++) a += red[i][u];
        float al = fsigmoid(ftanh(a));
        sal[u] = al;
        g_alpha[b * 4 + u] = al;
    }
    __syncthreads();
    // keys: thread -> (r = u>>6, m = u&63)
    const int r = u >> 6, m = u & 63;
    float acc = bk[r * M_ + m];
    const float* wk = Wk + (size_t)r * U_ * M_ + m;
    #pragma unroll 8
    for (int uu = 0; uu < U_; uu++) acc += hs[uu] * wk[uu * M_];
    float kt = ftanh(acc);
    g_kt[(r * B_ + b) * M_ + m] = kt;
    g_ktTh[(r * M_ + m) * B_ + b] = __float2half(kt * sal[r]);
    float s = kt * kt;
    #pragma unroll
    for (int o = 16; o > 0; o >>= 1) s += __shfl_xor_sync(0xffffffffu, s, o);
    if ((u & 31) == 0) sred[u >> 5] = s;
    __syncthreads();
    float inv = rsqrtf(sred[2 * r] + sred[2 * r + 1]);
    // pre-scale by log2(e): k_read uses ex2 (base-2) for the softmax exp
    g_ktsh[(r * B_ + b) * M_ + m] = __float2half(kt * inv * 1.44269504f);
}

// ---------------- K3: write deltas (tensor), software-pipelined ----------------
__global__ void __launch_bounds__(256) k_dA(const float* __restrict__ wrp) {
    __shared__ __align__(16) __half sP[64 * 136];   // [b-chunk 64][n 128 +8]
    __shared__ __align__(16) __half sA[64 * 72];    // [m 64][b-chunk 64 +8]
    const int t = threadIdx.x, w = t >> 5, l = t & 31;
    const int n0 = blockIdx.x * 128, r = blockIdx.y;
    const int mrow = (w & 3) * 16, nhalf = (w >> 2) * 64;
    const float* wr_base = wrp + (size_t)r * B_ * N_;
    float acc[8][4] = {};
    uint32_t pb = smem_u32(sP), ab = smem_u32(sA);

    const int prow = t >> 5, pc = t & 31;
    const int arow = t >> 3, ac4 = t & 7;
    float4 pv[8]; uint4 av[2];
    #pragma unroll
    for (int i = 0; i < 8; i++)
        pv[i] = *(const float4*)(wr_base + (size_t)(prow + i * 8) * N_ + n0 + pc * 4);
    #pragma unroll
    for (int i = 0; i < 2; i++)
        av[i] = *(const uint4*)(g_ktTh + (size_t)(r * M_ + arow + i * 32) * B_ + ac4 * 8);

    for (int kt = 0; kt < 4; kt++) {
        __syncthreads();
        #pragma unroll
        for (int i = 0; i < 8; i++) {
            int row = prow + i * 8;
            *(__half2*)(sP + row * 136 + pc * 4)     = __floats2half2_rn(pv[i].x, pv[i].y);
            *(__half2*)(sP + row * 136 + pc * 4 + 2) = __floats2half2_rn(pv[i].z, pv[i].w);
        }
        #pragma unroll
        for (int i = 0; i < 2; i++)
            *(uint4*)(sA + (arow + i * 32) * 72 + ac4 * 8) = av[i];
        __syncthreads();
        if (kt < 3) {
            int kb = (kt + 1) * 64;
            #pragma unroll
            for (int i = 0; i < 8; i++)
                pv[i] = *(const float4*)(wr_base + (size_t)(kb + prow + i * 8) * N_ + n0 + pc * 4);
            #pragma unroll
            for (int i = 0; i < 2; i++)
                av[i] = *(const uint4*)(g_ktTh + (size_t)(r * M_ + arow + i * 32) * B_ + kb + ac4 * 8);
        }
        #pragma unroll
        for (int k16 = 0; k16 < 4; k16++) {
            uint32_t a[4];
            ldsm4(a, ab + ((mrow + (l & 15)) * 72 + (l >> 4) * 8 + k16 * 16) * 2);
            #pragma unroll
            for (int j = 0; j < 4; j++) {
                uint32_t bb[4];
                int rowb = k16 * 16 + (l & 7) + ((l >> 3) & 1) * 8;
                int colb = nhalf + j * 16 + ((l >> 4) & 1) * 8;
                ldsm4t(bb, pb + (rowb * 136 + colb) * 2);
                mma16816(acc[2 * j],     a, bb[0], bb[1]);
                mma16816(acc[2 * j + 1], a, bb[2], bb[3]);
            }
        }
    }
    int m0 = mrow + (l >> 2), cb = n0 + nhalf + (l & 3) * 2;
    #pragma unroll
    for (int jj = 0; jj < 8; jj++) {
        *(__half2*)(g_dA + (size_t)(r * M_ + m0) * N_ + cb + jj * 8) =
            __floats2half2_rn(acc[jj][0], acc[jj][1]);
        *(__half2*)(g_dA + (size_t)(r * M_ + m0 + 8) * N_ + cb + jj * 8) =
            __floats2half2_rn(acc[jj][2], acc[jj][3]);
    }
}

// ---------------- K4a: argmin phase A — per-chunk partial first-min ----------------
// grid (B_, 4): block scans 8192 floats of row b. Also initializes emask.
__global__ void k_argmin_a(const float* __restrict__ wu) {
    int b = blockIdx.x, ch = blockIdx.y, t = threadIdx.x;
    const float4* row = (const float4*)(wu + (size_t)b * N_) + ch * 2048;
    const int base0 = ch * 8192;
    float mv = 3.4e38f; int mi = 0;
    #pragma unroll
    for (int i = t; i < 2048; i += 1024) {         // 2 outer iters, 4 loads each
        float4 v0 = row[i], v1 = row[i + 256], v2 = row[i + 512], v3 = row[i + 768];
        int b0 = base0 + i * 4, b1 = b0 + 1024, b2 = b0 + 2048, b3 = b0 + 3072;
        if (v0.x < mv) { mv = v0.x; mi = b0; }
        if (v0.y < mv) { mv = v0.y; mi = b0 + 1; }
        if (v0.z < mv) { mv = v0.z; mi = b0 + 2; }
        if (v0.w < mv) { mv = v0.w; mi = b0 + 3; }
        if (v1.x < mv) { mv = v1.x; mi = b1; }
        if (v1.y < mv) { mv = v1.y; mi = b1 + 1; }
        if (v1.z < mv) { mv = v1.z; mi = b1 + 2; }
        if (v1.w < mv) { mv = v1.w; mi = b1 + 3; }
        if (v2.x < mv) { mv = v2.x; mi = b2; }
        if (v2.y < mv) { mv = v2.y; mi = b2 + 1; }
        if (v2.z < mv) { mv = v2.z; mi = b2 + 2; }
        if (v2.w < mv) { mv = v2.w; mi = b2 + 3; }
        if (v3.x < mv) { mv = v3.x; mi = b3; }
        if (v3.y < mv) { mv = v3.y; mi = b3 + 1; }
        if (v3.z < mv) { mv = v3.z; mi = b3 + 2; }
        if (v3.w < mv) { mv = v3.w; mi = b3 + 3; }
    }
    __shared__ float sv[256];
    __shared__ int   si[256];
    sv[t] = mv; si[t] = mi;
    __syncthreads();
    for (int s = 128; s > 0; s >>= 1) {
        if (t < s) {
            if (sv[t + s] < sv[t] || (sv[t + s] == sv[t] && si[t + s] < si[t])) {
                sv[t] = sv[t + s]; si[t] = si[t + s];
            }
        }
        __syncthreads();
    }
    if (t == 0) {
        g_pminv[b * 4 + ch] = sv[0];
        g_pmini[b * 4 + ch] = si[0];
    }
    // emask init (grid covers N_ exactly: 256*4 blocks * 32 n each)
    if (t < 32) g_emask[(b * 4 + ch) * 32 + t] = 1.0f;
}

// ---------------- K4b: argmin phase B — combine 4 chunks (1 block) ----------------
__global__ void k_argmin_b() {
    int b = threadIdx.x;   // 256 threads
    float mv = g_pminv[b * 4]; int mi = g_pmini[b * 4];
    #pragma unroll
    for (int c = 1; c < 4; c++) {
        float v = g_pminv[b * 4 + c];
        if (v < mv) { mv = v; mi = g_pmini[b * 4 + c]; }   // strict <: lower chunk wins ties
    }
    g_least[b] = mi;
    g_emask[mi] = 0.0f;       // duplicate writers store same value: deterministic
}

// ---------------- K5: deterministic least-used scatter into g_dA ----------------
__global__ void k_scatter() {
    const int r = blockIdx.y;
    __shared__ int sL[B_];
    int t = threadIdx.x, b = blockIdx.x;
    sL[t] = g_least[t];
    __syncthreads();
    int my = sL[b];
    bool owner = true;
    for (int bb = 0; bb < b; bb++) if (sL[bb] == my) { owner = false; break; }
    if (!owner) return;
    if (t < M_) {
        float acc = 0.0f;
        for (int bb = b; bb < B_; bb++)
            if (sL[bb] == my)
                acc += (1.0f - g_alpha[bb * R_ + r]) * g_kt[((r << 8) + bb) * M_ + t];
        size_t o = (size_t)(r * M_ + t) * N_ + my;
        g_dA[o] = __float2half(__half2float(g_dA[o]) + acc);
    }
}

// ---------------- K6: chain (+fused Ash): AnT = fp16(tanh^4 chain), Ash = A/||A|| -----
__global__ void k_chain(const float* __restrict__ A) {
    __shared__ float sT[64][65];
    __shared__ float se[64];
    int t = threadIdx.x, n0 = blockIdx.x * 64;
    int w = t >> 5, l = t & 31;
    for (int idx = t; idx < 4096; idx += 256) {
        int row = idx >> 6, c = idx & 63;
        sT[row][c] = A[(size_t)(n0 + row) * M_ + c];
    }
    if (t < 64) se[t] = g_emask[n0 + t];
    __syncthreads();
    #pragma unroll
    for (int rr = 0; rr < 8; rr++) {
        int row = w * 8 + rr;
        float a0 = sT[row][l], a1 = sT[row][32 + l];
        float s = a0 * a0 + a1 * a1;
        #pragma unroll
        for (int o = 16; o > 0; o >>= 1) s += __shfl_xor_sync(0xffffffffu, s, o);
        float inv = rsqrtf(s);
        g_Ash[(size_t)(n0 + row) * M_ + l]      = __float2half(a0 * inv);
        g_Ash[(size_t)(n0 + row) * M_ + 32 + l] = __float2half(a1 * inv);
    }
    for (int idx = t; idx < 4096; idx += 256) {
        int m = idx >> 6, n = idx & 63;
        float a = sT[n][m] * se[n];
        #pragma unroll
        for (int r = 0; r < 4; r++)
            a = htanh(a + __half2float(g_dA[(size_t)(r * M_ + m) * N_ + n0 + n]));
        g_AnT[(size_t)m * N_ + n0 + n] = __float2half(a);
    }
}

// ---------------- K7: flash fused reads; ex2.f16x2 softmax ----------------
__global__ void __launch_bounds__(256, 2) k_read() {
    __shared__ __align__(16) __half sQ[128 * 72];
    __shared__ __align__(16) __half sK[2][128 * 72];
    __shared__ __align__(16) __half sV[2][64 * 136];
    const int t = threadIdx.x, w = t >> 5, l = t & 31;
    const int q0 = blockIdx.y * 128, n0 = blockIdx.x * 1024;
    uint32_t qb = smem_u32(sQ);

    for (int idx = t; idx < 1024; idx += 256) {
        int row = idx >> 3, c4 = idx & 7;
        cpa16(qb + (row * 72 + c4 * 8) * 2, g_ktsh + (size_t)(q0 + row) * M_ + c4 * 8);
    }
    {
        uint32_t kb = smem_u32(sK[0]), vb = smem_u32(sV[0]);
        for (int idx = t; idx < 1024; idx += 256) {
            int row = idx >> 3, c4 = idx & 7;
            cpa16(kb + (row * 72 + c4 * 8) * 2, g_Ash + (size_t)(n0 + row) * M_ + c4 * 8);
        }
        for (int idx = t; idx < 1024; idx += 256) {
            int row = idx >> 4, c4 = idx & 15;
            cpa16(vb + (row * 136 + c4 * 8) * 2, g_AnT + (size_t)row * N_ + n0 + c4 * 8);
        }
    }
    CP_COMMIT();

    uint32_t qa[4][4];
    float acc_o[8][4] = {};
    float den0 = 0.0f, den1 = 0.0f;
    for (int sub = 0; sub < 8; sub++) {
        if (sub + 1 < 8) {
            int kg = n0 + (sub + 1) * 128;
            uint32_t kb = smem_u32(sK[(sub + 1) & 1]), vb = smem_u32(sV[(sub + 1) & 1]);
            for (int idx = t; idx < 1024; idx += 256) {
                int row = idx >> 3, c4 = idx & 7;
                cpa16(kb + (row * 72 + c4 * 8) * 2, g_Ash + (size_t)(kg + row) * M_ + c4 * 8);
            }
            for (int idx = t; idx < 1024; idx += 256) {
                int row = idx >> 4, c4 = idx & 15;
                cpa16(vb + (row * 136 + c4 * 8) * 2, g_AnT + (size_t)row * N_ + kg + c4 * 8);
            }
        }
        CP_COMMIT();
        CP_WAIT(1);
        __syncthreads();
        if (sub == 0) {
            #pragma unroll
            for (int k16 = 0; k16 < 4; k16++)
                ldsm4(qa[k16], qb + ((w * 16 + (l & 15)) * 72 + (l >> 4) * 8 + k16 * 16) * 2);
        }
        uint32_t kb = smem_u32(sK[sub & 1]), vb = smem_u32(sV[sub & 1]);
        float s[16][4] = {};
        #pragma unroll
        for (int k16 = 0; k16 < 4; k16++) {
            #pragma unroll
            for (int j = 0; j < 8; j++) {
                uint32_t bbf[4];
                ldsm4(bbf, kb + ((j * 16 + (l & 15)) * 72 + (l >> 4) * 8 + k16 * 16) * 2);
                mma16816(s[2 * j],     qa[k16], bbf[0], bbf[2]);
                mma16816(s[2 * j + 1], qa[k16], bbf[1], bbf[3]);
            }
        }
        // P = 2^S in packed fp16 (Q pre-scaled by log2e); den in fp32
        #pragma unroll
        for (int kk = 0; kk < 8; kk++) {
            uint32_t pa[4];
            pa[0] = packh2(s[2 * kk][0],     s[2 * kk][1]);
            pa[1] = packh2(s[2 * kk][2],     s[2 * kk][3]);
            pa[2] = packh2(s[2 * kk + 1][0], s[2 * kk + 1][1]);
            pa[3] = packh2(s[2 * kk + 1][2], s[2 * kk + 1][3]);
            #pragma unroll
            for (int i = 0; i < 4; i++)
                asm("ex2.approx.f16x2 %0, %0;" : "+r"(pa[i]));
            float2 f0 = __half22float2(*(__half2*)&pa[0]);
            float2 f1 = __half22float2(*(__half2*)&pa[1]);
            float2 f2 = __half22float2(*(__half2*)&pa[2]);
            float2 f3 = __half22float2(*(__half2*)&pa[3]);
            den0 += f0.x + f0.y + f2.x + f2.y;
            den1 += f1.x + f1.y + f3.x + f3.y;
            #pragma unroll
            for (int j = 0; j < 4; j++) {
                uint32_t bbf[4];
                ldsm4(bbf, vb + ((j * 16 + (l & 15)) * 136 + (l >> 4) * 8 + kk * 16) * 2);
                mma16816(acc_o[2 * j],     pa, bbf[0], bbf[2]);
                mma16816(acc_o[2 * j + 1], pa, bbf[1], bbf[3]);
            }
        }
        __syncthreads();
    }
    den0 += __shfl_xor_sync(0xffffffffu, den0, 1);
    den0 += __shfl_xor_sync(0xffffffffu, den0, 2);
    den1 += __shfl_xor_sync(0xffffffffu, den1, 1);
    den1 += __shfl_xor_sync(0xffffffffu, den1, 2);
    int r0 = q0 + w * 16 + (l >> 2);
    if ((l & 3) == 0) {
        g_pden[r0 * NSPL + blockIdx.x]       = den0;
        g_pden[(r0 + 8) * NSPL + blockIdx.x] = den1;
    }
    float* p0 = g_pacc + ((size_t)r0 * NSPL + blockIdx.x) * M_;
    float* p1 = g_pacc + ((size_t)(r0 + 8) * NSPL + blockIdx.x) * M_;
    int cb = (l & 3) * 2;
    #pragma unroll
    for (int jj = 0; jj < 8; jj++) {
        *(float2*)(p0 + jj * 8 + cb) = make_float2(acc_o[jj][0], acc_o[jj][1]);
        *(float2*)(p1 + jj * 8 + cb) = make_float2(acc_o[jj][2], acc_o[jj][3]);
    }
}

// ---------------- K8: combine partials -> out[:, 256:512] ----------------
__global__ void k_combine(float* __restrict__ out) {
    int q = blockIdx.x;          // r*B + b
    int m = threadIdx.x;         // 64
    float acc = 0.0f, den = 0.0f;
    #pragma unroll
    for (int s = 0; s < NSPL; s++) {
        acc += g_pacc[((size_t)q * NSPL + s) * M_ + m];
        den += g_pden[q * NSPL + s];
    }
    int r = q >> 8, b = q & 255;
    out[b * 512 + 256 + r * M_ + m] = acc / den;
}

// ---------------- launch ----------------
extern "C" void kernel_launch(void* const* d_in, const int* in_sizes, int n_in,
                              void* d_out, int out_size) {
    const float* x    = (const float*)d_in[0];
    const float* A    = (const float*)d_in[1];
    const float* wrp  = (const float*)d_in[2];
    const float* wu   = (const float*)d_in[3];
    const float* rp   = (const float*)d_in[4];
    const float* h    = (const float*)d_in[5];
    const float* c    = (const float*)d_in[6];
    const float* W    = (const float*)d_in[7];
    const float* Uw   = (const float*)d_in[8];
    const float* bias = (const float*)d_in[9];
    const float* Wk   = (const float*)d_in[10];
    const float* bk   = (const float*)d_in[11];
    const float* Wa   = (const float*)d_in[12];
    const float* ba   = (const float*)d_in[13];
    float* out = (float*)d_out;

    k_gates_mma<<<dim3(8, 2, KSPL), 256>>>(x, rp, h, W, Uw);      // 0
    k_lstm_kt  <<<B_, 256>>>(c, out, Wa, ba, Wk, bk, bias);       // 1
    k_dA       <<<dim3(N_ / 128, R_), 256>>>(wrp);                // 2
    k_argmin_a <<<dim3(B_, 4), 256>>>(wu);                        // 3 <- profiled slot
    k_argmin_b <<<1, 256>>>();                                    // 4
    k_scatter  <<<dim3(B_, R_), 256>>>();                         // 5
    k_chain    <<<N_ / 64, 256>>>(A);                             // 6
    k_read     <<<dim3(NSPL, 8), 256>>>();                        // 7
    k_combine  <<<QT_, 64>>>(out);                                // 8
}

// round 12
// speedup vs baseline: 1.0330x; 1.0330x over previous
#include <cuda_runtime.h>
#include <cuda_fp16.h>
#include <math.h>
#include <stdint.h>

// Problem constants
#define B_   256
#define N_   32768
#define M_   64
#define R_   4
#define U_   256
#define DIN_ 512
#define G4_  1024
#define QT_  1024      // total queries = R*B
#define NSPL 32        // flash reads: split of N (1024 keys per chunk)
#define KSPL 8         // gates GEMM split-K parts
#define ONESH2 0x3C003C00u   // half2(1.0, 1.0)

// ---------------- static scratch ----------------
__device__ float  g_gpart[KSPL * B_ * G4_];   // gates split-K partials (8 MB)
__device__ float  g_kt   [QT_ * M_];          // raw tanh keys fp32 (scatter)
__device__ __half g_ktsh [QT_ * M_];          // normalized keys * log2e, fp16 [q][m]
__device__ __half g_ktTh [R_ * M_ * B_];      // alpha-scaled keys fp16 [r][m][b]
__device__ float  g_alpha[B_ * R_];
__device__ int    g_least[B_];
__device__ float  g_pminv[B_ * 4];            // argmin chunk partial values
__device__ int    g_pmini[B_ * 4];            // argmin chunk partial indices
__device__ __half g_Ash  [N_ * M_];           // A rows / ||A[n]|| fp16 [n][m]
__device__ __half g_dA   [R_ * M_ * N_];      // write deltas fp16 [r][m][n]
__device__ float  g_emask[N_];
__device__ __half g_AnT  [M_ * N_];           // new memory fp16 [m][n]
__device__ float  g_pden [QT_ * NSPL];
__device__ float  g_pacc [QT_ * NSPL * M_];

// fast transcendentals
__device__ __forceinline__ float fsigmoid(float x) {
    return __fdividef(1.0f, 1.0f + __expf(-x));
}
__device__ __forceinline__ float ftanh(float x) {
    float e = __expf(2.0f * x);
    return __fdividef(e - 1.0f, e + 1.0f);
}
__device__ __forceinline__ float htanh(float x) {     // MUFU.TANH, 1 op
    float y;
    asm("tanh.approx.f32 %0, %1;" : "=f"(y) : "f"(x));
    return y;
}

__device__ __forceinline__ uint32_t smem_u32(const void* p) {
    uint32_t a;
    asm("{ .reg .u64 t; cvta.to.shared.u64 t, %1; cvt.u32.u64 %0, t; }" : "=r"(a) : "l"(p));
    return a;
}
__device__ __forceinline__ void ldsm4(uint32_t* r, uint32_t addr) {
    asm volatile("ldmatrix.sync.aligned.m8n8.x4.shared.b16 {%0,%1,%2,%3}, [%4];"
        : "=r"(r[0]), "=r"(r[1]), "=r"(r[2]), "=r"(r[3]) : "r"(addr));
}
__device__ __forceinline__ void ldsm4t(uint32_t* r, uint32_t addr) {
    asm volatile("ldmatrix.sync.aligned.m8n8.x4.trans.shared.b16 {%0,%1,%2,%3}, [%4];"
        : "=r"(r[0]), "=r"(r[1]), "=r"(r[2]), "=r"(r[3]) : "r"(addr));
}
__device__ __forceinline__ void mma16816(float* c, const uint32_t* a, uint32_t b0, uint32_t b1) {
    asm volatile("mma.sync.aligned.m16n8k16.row.col.f32.f16.f16.f32 "
        "{%0,%1,%2,%3}, {%4,%5,%6,%7}, {%8,%9}, {%0,%1,%2,%3};"
        : "+f"(c[0]), "+f"(c[1]), "+f"(c[2]), "+f"(c[3])
        : "r"(a[0]), "r"(a[1]), "r"(a[2]), "r"(a[3]), "r"(b0), "r"(b1));
}
__device__ __forceinline__ uint32_t packh2(float a, float b) {
    __half2 h = __floats2half2_rn(a, b);
    return *(uint32_t*)&h;
}
__device__ __forceinline__ void cpa16(uint32_t dst, const void* src) {
    asm volatile("cp.async.ca.shared.global [%0], [%1], 16;" :: "r"(dst), "l"(src));
}
#define CP_COMMIT() asm volatile("cp.async.commit_group;" ::: "memory")
#define CP_WAIT(n)  asm volatile("cp.async.wait_group %0;" :: "n"(n) : "memory")

// ---------------- K1: gates GEMM on tensor cores, split-K ----------------
__global__ void __launch_bounds__(256) k_gates_mma(
        const float* __restrict__ x, const float* __restrict__ rp,
        const float* __restrict__ h, const float* __restrict__ W,
        const float* __restrict__ Uw) {
    __shared__ __align__(16) __half sIn[128 * 24];   // [row 128][k 16 +8]
    __shared__ __align__(16) __half sW [16 * 136];   // [k 16][col 128 +8]
    const int t = threadIdx.x, w = t >> 5, l = t & 31;
    const int j0 = blockIdx.x * 128, b0 = blockIdx.y * 128, z = blockIdx.z;
    uint32_t ib = smem_u32(sIn), wb = smem_u32(sW);

    const int irow = t >> 1,  icol = (t & 1) * 8;
    const int wrow = t >> 4,  wcol = (t & 15) * 8;

    float4 iv0, iv1, wv0, wv1;
    auto ld_in = [&](int k0) {
        const float* s;
        if (k0 < DIN_)      s = x + (size_t)(b0 + irow) * DIN_ + k0 + icol;
        else if (k0 < 768) { int i0 = k0 - DIN_;
                            s = rp + ((size_t)(i0 >> 6) * B_ + b0 + irow) * M_ + (i0 & 63) + icol; }
        else                s = h + (size_t)(b0 + irow) * U_ + (k0 - 768) + icol;
        iv0 = *(const float4*)s; iv1 = *(const float4*)(s + 4);
    };
    auto ld_w = [&](int k0) {
        int kk = k0 + wrow;
        const float* s = (kk < 768) ? W + (size_t)kk * G4_ + j0 + wcol
                                    : Uw + (size_t)(kk - 768) * G4_ + j0 + wcol;
        wv0 = *(const float4*)s; wv1 = *(const float4*)(s + 4);
    };

    const int kt0 = z * (64 / KSPL);
    ld_in(kt0 * 16); ld_w(kt0 * 16);
    float acc[16][4] = {};
    for (int kt = 0; kt < 64 / KSPL; kt++) {
        __syncthreads();
        {
            uint4 o;
            o.x = packh2(iv0.x, iv0.y); o.y = packh2(iv0.z, iv0.w);
            o.z = packh2(iv1.x, iv1.y); o.w = packh2(iv1.z, iv1.w);
            *(uint4*)(sIn + irow * 24 + icol) = o;
            o.x = packh2(wv0.x, wv0.y); o.y = packh2(wv0.z, wv0.w);
            o.z = packh2(wv1.x, wv1.y); o.w = packh2(wv1.z, wv1.w);
            *(uint4*)(sW + wrow * 136 + wcol) = o;
        }
        __syncthreads();
        if (kt < 64 / KSPL - 1) { ld_in((kt0 + kt + 1) * 16); ld_w((kt0 + kt + 1) * 16); }
        uint32_t a[4];
        ldsm4(a, ib + ((w * 16 + (l & 15)) * 24 + (l >> 4) * 8) * 2);
        #pragma unroll
        for (int j = 0; j < 8; j++) {
            uint32_t bb[4];
            int rowb = (l & 7) + ((l >> 3) & 1) * 8;
            int colb = j * 16 + ((l >> 4) & 1) * 8;
            ldsm4t(bb, wb + (rowb * 136 + colb) * 2);
            mma16816(acc[2 * j],     a, bb[0], bb[1]);
            mma16816(acc[2 * j + 1], a, bb[2], bb[3]);
        }
    }
    int mr = w * 16 + (l >> 2);
    float* gp = g_gpart + (size_t)z * B_ * G4_;
    int row0 = b0 + mr, row1 = row0 + 8;
    #pragma unroll
    for (int i = 0; i < 16; i++) {
        int col = j0 + i * 8 + (l & 3) * 2;
        *(float2*)(gp + (size_t)row0 * G4_ + col) = make_float2(acc[i][0], acc[i][1]);
        *(float2*)(gp + (size_t)row1 * G4_ + col) = make_float2(acc[i][2], acc[i][3]);
    }
}

// ---------------- K2: fused LSTM + alpha + keys (block = one batch row) ----------------
__global__ void __launch_bounds__(256) k_lstm_kt(
        const float* __restrict__ c, float* __restrict__ out,
        const float* __restrict__ Wa, const float* __restrict__ ba,
        const float* __restrict__ Wk, const float* __restrict__ bk,
        const float* __restrict__ bias) {
    __shared__ float hs[256];
    __shared__ float red[8][4];
    __shared__ float sal[4];
    __shared__ float sred[8];
    const int b = blockIdx.x, u = threadIdx.x;
    const int idx = b * 256 + u;
    float gi = bias[u], gf = bias[256 + u], gg = bias[512 + u], go = bias[768 + u];
    #pragma unroll
    for (int p = 0; p < KSPL; p++) {
        const float* gp = g_gpart + (size_t)p * B_ * G4_ + (size_t)b * G4_;
        gi += gp[u]; gf += gp[256 + u]; gg += gp[512 + u]; go += gp[768 + u];
    }
    float cn = fsigmoid(gf) * c[idx] + fsigmoid(gi) * ftanh(gg);
    float hn = fsigmoid(go) * ftanh(cn);
    hs[u] = hn;
    out[b * 512 + u] = hn;
    // alpha partials
    float4 w4 = *(const float4*)(Wa + u * 4);
    float p0 = hn * w4.x, p1 = hn * w4.y, p2 = hn * w4.z, p3 = hn * w4.w;
    #pragma unroll
    for (int o = 16; o > 0; o >>= 1) {
        p0 += __shfl_xor_sync(0xffffffffu, p0, o);
        p1 += __shfl_xor_sync(0xffffffffu, p1, o);
        p2 += __shfl_xor_sync(0xffffffffu, p2, o);
        p3 += __shfl_xor_sync(0xffffffffu, p3, o);
    }
    if ((u & 31) == 0) {
        red[u >> 5][0] = p0; red[u >> 5][1] = p1;
        red[u >> 5][2] = p2; red[u >> 5][3] = p3;
    }
    __syncthreads();
    if (u < 4) {
        float a = ba[u];
        #pragma unroll
        for (int i = 0; i < 8; i++) a += red[i][u];
        float al = fsigmoid(ftanh(a));
        sal[u] = al;
        g_alpha[b * 4 + u] = al;
    }
    __syncthreads();
    // keys: thread -> (r = u>>6, m = u&63)
    const int r = u >> 6, m = u & 63;
    float acc = bk[r * M_ + m];
    const float* wk = Wk + (size_t)r * U_ * M_ + m;
    #pragma unroll 8
    for (int uu = 0; uu < U_; uu++) acc += hs[uu] * wk[uu * M_];
    float kt = ftanh(acc);
    g_kt[(r * B_ + b) * M_ + m] = kt;
    g_ktTh[(r * M_ + m) * B_ + b] = __float2half(kt * sal[r]);
    float s = kt * kt;
    #pragma unroll
    for (int o = 16; o > 0; o >>= 1) s += __shfl_xor_sync(0xffffffffu, s, o);
    if ((u & 31) == 0) sred[u >> 5] = s;
    __syncthreads();
    float inv = rsqrtf(sred[2 * r] + sred[2 * r + 1]);
    // pre-scale by log2(e): k_read uses ex2 (base-2) for the softmax exp
    g_ktsh[(r * B_ + b) * M_ + m] = __float2half(kt * inv * 1.44269504f);
}

// ---------------- K3: write deltas (tensor), software-pipelined ----------------
__global__ void __launch_bounds__(256) k_dA(const float* __restrict__ wrp) {
    __shared__ __align__(16) __half sP[64 * 136];   // [b-chunk 64][n 128 +8]
    __shared__ __align__(16) __half sA[64 * 72];    // [m 64][b-chunk 64 +8]
    const int t = threadIdx.x, w = t >> 5, l = t & 31;
    const int n0 = blockIdx.x * 128, r = blockIdx.y;
    const int mrow = (w & 3) * 16, nhalf = (w >> 2) * 64;
    const float* wr_base = wrp + (size_t)r * B_ * N_;
    float acc[8][4] = {};
    uint32_t pb = smem_u32(sP), ab = smem_u32(sA);

    const int prow = t >> 5, pc = t & 31;
    const int arow = t >> 3, ac4 = t & 7;
    float4 pv[8]; uint4 av[2];
    #pragma unroll
    for (int i = 0; i < 8; i++)
        pv[i] = *(const float4*)(wr_base + (size_t)(prow + i * 8) * N_ + n0 + pc * 4);
    #pragma unroll
    for (int i = 0; i < 2; i++)
        av[i] = *(const uint4*)(g_ktTh + (size_t)(r * M_ + arow + i * 32) * B_ + ac4 * 8);

    for (int kt = 0; kt < 4; kt++) {
        __syncthreads();
        #pragma unroll
        for (int i = 0; i < 8; i++) {
            int row = prow + i * 8;
            *(__half2*)(sP + row * 136 + pc * 4)     = __floats2half2_rn(pv[i].x, pv[i].y);
            *(__half2*)(sP + row * 136 + pc * 4 + 2) = __floats2half2_rn(pv[i].z, pv[i].w);
        }
        #pragma unroll
        for (int i = 0; i < 2; i++)
            *(uint4*)(sA + (arow + i * 32) * 72 + ac4 * 8) = av[i];
        __syncthreads();
        if (kt < 3) {
            int kb = (kt + 1) * 64;
            #pragma unroll
            for (int i = 0; i < 8; i++)
                pv[i] = *(const float4*)(wr_base + (size_t)(kb + prow + i * 8) * N_ + n0 + pc * 4);
            #pragma unroll
            for (int i = 0; i < 2; i++)
                av[i] = *(const uint4*)(g_ktTh + (size_t)(r * M_ + arow + i * 32) * B_ + kb + ac4 * 8);
        }
        #pragma unroll
        for (int k16 = 0; k16 < 4; k16++) {
            uint32_t a[4];
            ldsm4(a, ab + ((mrow + (l & 15)) * 72 + (l >> 4) * 8 + k16 * 16) * 2);
            #pragma unroll
            for (int j = 0; j < 4; j++) {
                uint32_t bb[4];
                int rowb = k16 * 16 + (l & 7) + ((l >> 3) & 1) * 8;
                int colb = nhalf + j * 16 + ((l >> 4) & 1) * 8;
                ldsm4t(bb, pb + (rowb * 136 + colb) * 2);
                mma16816(acc[2 * j],     a, bb[0], bb[1]);
                mma16816(acc[2 * j + 1], a, bb[2], bb[3]);
            }
        }
    }
    int m0 = mrow + (l >> 2), cb = n0 + nhalf + (l & 3) * 2;
    #pragma unroll
    for (int jj = 0; jj < 8; jj++) {
        *(__half2*)(g_dA + (size_t)(r * M_ + m0) * N_ + cb + jj * 8) =
            __floats2half2_rn(acc[jj][0], acc[jj][1]);
        *(__half2*)(g_dA + (size_t)(r * M_ + m0 + 8) * N_ + cb + jj * 8) =
            __floats2half2_rn(acc[jj][2], acc[jj][3]);
    }
}

// ---------------- K4a: argmin phase A — 4 independent chains, per-chunk first-min -----
// grid (B_, 4): block scans 8192 floats of row b. Also initializes emask.
__global__ void k_argmin_a(const float* __restrict__ wu) {
    int b = blockIdx.x, ch = blockIdx.y, t = threadIdx.x;
    const float4* row = (const float4*)(wu + (size_t)b * N_) + ch * 2048;
    const int base0 = ch * 8192;
    float m0 = 3.4e38f, m1 = 3.4e38f, m2 = 3.4e38f, m3 = 3.4e38f;
    int i0 = 0, i1 = 0, i2 = 0, i3 = 0;
    #pragma unroll
    for (int i = t; i < 2048; i += 1024) {         // 2 outer iters, 4 indep chains
        float4 v0 = row[i], v1 = row[i + 256], v2 = row[i + 512], v3 = row[i + 768];
        int b0 = base0 + i * 4, b1 = b0 + 1024, b2 = b0 + 2048, b3 = b0 + 3072;
        if (v0.x < m0) { m0 = v0.x; i0 = b0; }
        if (v0.y < m0) { m0 = v0.y; i0 = b0 + 1; }
        if (v0.z < m0) { m0 = v0.z; i0 = b0 + 2; }
        if (v0.w < m0) { m0 = v0.w; i0 = b0 + 3; }
        if (v1.x < m1) { m1 = v1.x; i1 = b1; }
        if (v1.y < m1) { m1 = v1.y; i1 = b1 + 1; }
        if (v1.z < m1) { m1 = v1.z; i1 = b1 + 2; }
        if (v1.w < m1) { m1 = v1.w; i1 = b1 + 3; }
        if (v2.x < m2) { m2 = v2.x; i2 = b2; }
        if (v2.y < m2) { m2 = v2.y; i2 = b2 + 1; }
        if (v2.z < m2) { m2 = v2.z; i2 = b2 + 2; }
        if (v2.w < m2) { m2 = v2.w; i2 = b2 + 3; }
        if (v3.x < m3) { m3 = v3.x; i3 = b3; }
        if (v3.y < m3) { m3 = v3.y; i3 = b3 + 1; }
        if (v3.z < m3) { m3 = v3.z; i3 = b3 + 2; }
        if (v3.w < m3) { m3 = v3.w; i3 = b3 + 3; }
    }
    // merge 4 chains lexicographically (value, index)
    float mv = m0; int mi = i0;
    if (m1 < mv || (m1 == mv && i1 < mi)) { mv = m1; mi = i1; }
    if (m2 < mv || (m2 == mv && i2 < mi)) { mv = m2; mi = i2; }
    if (m3 < mv || (m3 == mv && i3 < mi)) { mv = m3; mi = i3; }
    __shared__ float sv[256];
    __shared__ int   si[256];
    sv[t] = mv; si[t] = mi;
    __syncthreads();
    for (int s = 128; s > 0; s >>= 1) {
        if (t < s) {
            if (sv[t + s] < sv[t] || (sv[t + s] == sv[t] && si[t + s] < si[t])) {
                sv[t] = sv[t + s]; si[t] = si[t + s];
            }
        }
        __syncthreads();
    }
    if (t == 0) {
        g_pminv[b * 4 + ch] = sv[0];
        g_pmini[b * 4 + ch] = si[0];
    }
    // emask init (grid covers N_ exactly: 256*4 blocks * 32 n each)
    if (t < 32) g_emask[(b * 4 + ch) * 32 + t] = 1.0f;
}

// ---------------- K4b: argmin phase B — combine 4 chunks (1 block) ----------------
__global__ void k_argmin_b() {
    int b = threadIdx.x;   // 256 threads
    float mv = g_pminv[b * 4]; int mi = g_pmini[b * 4];
    #pragma unroll
    for (int c = 1; c < 4; c++) {
        float v = g_pminv[b * 4 + c];
        if (v < mv) { mv = v; mi = g_pmini[b * 4 + c]; }   // strict <: lower chunk wins ties
    }
    g_least[b] = mi;
    g_emask[mi] = 0.0f;       // duplicate writers store same value: deterministic
}

// ---------------- K5: deterministic least-used scatter into g_dA ----------------
__global__ void k_scatter() {
    const int r = blockIdx.y;
    __shared__ int sL[B_];
    int t = threadIdx.x, b = blockIdx.x;
    sL[t] = g_least[t];
    __syncthreads();
    int my = sL[b];
    bool owner = true;
    for (int bb = 0; bb < b; bb++) if (sL[bb] == my) { owner = false; break; }
    if (!owner) return;
    if (t < M_) {
        float acc = 0.0f;
        for (int bb = b; bb < B_; bb++)
            if (sL[bb] == my)
                acc += (1.0f - g_alpha[bb * R_ + r]) * g_kt[((r << 8) + bb) * M_ + t];
        size_t o = (size_t)(r * M_ + t) * N_ + my;
        g_dA[o] = __float2half(__half2float(g_dA[o]) + acc);
    }
}

// ---------------- K6: chain (+fused Ash): AnT = fp16(tanh^4 chain), Ash = A/||A|| -----
__global__ void k_chain(const float* __restrict__ A) {
    __shared__ float sT[64][65];
    __shared__ float se[64];
    int t = threadIdx.x, n0 = blockIdx.x * 64;
    int w = t >> 5, l = t & 31;
    for (int idx = t; idx < 4096; idx += 256) {
        int row = idx >> 6, c = idx & 63;
        sT[row][c] = A[(size_t)(n0 + row) * M_ + c];
    }
    if (t < 64) se[t] = g_emask[n0 + t];
    __syncthreads();
    #pragma unroll
    for (int rr = 0; rr < 8; rr++) {
        int row = w * 8 + rr;
        float a0 = sT[row][l], a1 = sT[row][32 + l];
        float s = a0 * a0 + a1 * a1;
        #pragma unroll
        for (int o = 16; o > 0; o >>= 1) s += __shfl_xor_sync(0xffffffffu, s, o);
        float inv = rsqrtf(s);
        g_Ash[(size_t)(n0 + row) * M_ + l]      = __float2half(a0 * inv);
        g_Ash[(size_t)(n0 + row) * M_ + 32 + l] = __float2half(a1 * inv);
    }
    for (int idx = t; idx < 4096; idx += 256) {
        int m = idx >> 6, n = idx & 63;
        float a = sT[n][m] * se[n];
        #pragma unroll
        for (int r = 0; r < 4; r++)
            a = htanh(a + __half2float(g_dA[(size_t)(r * M_ + m) * N_ + n0 + n]));
        g_AnT[(size_t)m * N_ + n0 + n] = __float2half(a);
    }
}

// ---------------- K7: flash fused reads; ex2.f16x2 softmax, den via ones-MMA ----------
__global__ void __launch_bounds__(256, 2) k_read() {
    __shared__ __align__(16) __half sQ[128 * 72];
    __shared__ __align__(16) __half sK[2][128 * 72];
    __shared__ __align__(16) __half sV[2][64 * 136];
    const int t = threadIdx.x, w = t >> 5, l = t & 31;
    const int q0 = blockIdx.y * 128, n0 = blockIdx.x * 1024;
    uint32_t qb = smem_u32(sQ);

    for (int idx = t; idx < 1024; idx += 256) {
        int row = idx >> 3, c4 = idx & 7;
        cpa16(qb + (row * 72 + c4 * 8) * 2, g_ktsh + (size_t)(q0 + row) * M_ + c4 * 8);
    }
    {
        uint32_t kb = smem_u32(sK[0]), vb = smem_u32(sV[0]);
        for (int idx = t; idx < 1024; idx += 256) {
            int row = idx >> 3, c4 = idx & 7;
            cpa16(kb + (row * 72 + c4 * 8) * 2, g_Ash + (size_t)(n0 + row) * M_ + c4 * 8);
        }
        for (int idx = t; idx < 1024; idx += 256) {
            int row = idx >> 4, c4 = idx & 15;
            cpa16(vb + (row * 136 + c4 * 8) * 2, g_AnT + (size_t)row * N_ + n0 + c4 * 8);
        }
    }
    CP_COMMIT();

    uint32_t qa[4][4];
    float acc_o[8][4] = {};
    float acc_d[4] = {};          // denominator via ones-column MMA
    for (int sub = 0; sub < 8; sub++) {
        if (sub + 1 < 8) {
            int kg = n0 + (sub + 1) * 128;
            uint32_t kb = smem_u32(sK[(sub + 1) & 1]), vb = smem_u32(sV[(sub + 1) & 1]);
            for (int idx = t; idx < 1024; idx += 256) {
                int row = idx >> 3, c4 = idx & 7;
                cpa16(kb + (row * 72 + c4 * 8) * 2, g_Ash + (size_t)(kg + row) * M_ + c4 * 8);
            }
            for (int idx = t; idx < 1024; idx += 256) {
                int row = idx >> 4, c4 = idx & 15;
                cpa16(vb + (row * 136 + c4 * 8) * 2, g_AnT + (size_t)row * N_ + kg + c4 * 8);
            }
        }
        CP_COMMIT();
        CP_WAIT(1);
        __syncthreads();
        if (sub == 0) {
            #pragma unroll
            for (int k16 = 0; k16 < 4; k16++)
                ldsm4(qa[k16], qb + ((w * 16 + (l & 15)) * 72 + (l >> 4) * 8 + k16 * 16) * 2);
        }
        uint32_t kb = smem_u32(sK[sub & 1]), vb = smem_u32(sV[sub & 1]);
        float s[16][4] = {};
        #pragma unroll
        for (int k16 = 0; k16 < 4; k16++) {
            #pragma unroll
            for (int j = 0; j < 8; j++) {
                uint32_t bbf[4];
                ldsm4(bbf, kb + ((j * 16 + (l & 15)) * 72 + (l >> 4) * 8 + k16 * 16) * 2);
                mma16816(s[2 * j],     qa[k16], bbf[0], bbf[2]);
                mma16816(s[2 * j + 1], qa[k16], bbf[1], bbf[3]);
            }
        }
        // P = 2^S packed fp16 (Q pre-scaled by log2e); den & O via MMA
        #pragma unroll
        for (int kk = 0; kk < 8; kk++) {
            uint32_t pa[4];
            pa[0] = packh2(s[2 * kk][0],     s[2 * kk][1]);
            pa[1] = packh2(s[2 * kk][2],     s[2 * kk][3]);
            pa[2] = packh2(s[2 * kk + 1][0], s[2 * kk + 1][1]);
            pa[3] = packh2(s[2 * kk + 1][2], s[2 * kk + 1][3]);
            #pragma unroll
            for (int i = 0; i < 4; i++)
                asm("ex2.approx.f16x2 %0, %0;" : "+r"(pa[i]));
            mma16816(acc_d, pa, ONESH2, ONESH2);     // den += P @ ones
            #pragma unroll
            for (int j = 0; j < 4; j++) {
                uint32_t bbf[4];
                ldsm4(bbf, vb + ((j * 16 + (l & 15)) * 136 + (l >> 4) * 8 + kk * 16) * 2);
                mma16816(acc_o[2 * j],     pa, bbf[0], bbf[2]);
                mma16816(acc_o[2 * j + 1], pa, bbf[1], bbf[3]);
            }
        }
        __syncthreads();
    }
    int r0 = q0 + w * 16 + (l >> 2);
    if ((l & 3) == 0) {
        g_pden[r0 * NSPL + blockIdx.x]       = acc_d[0];
        g_pden[(r0 + 8) * NSPL + blockIdx.x] = acc_d[2];
    }
    float* p0 = g_pacc + ((size_t)r0 * NSPL + blockIdx.x) * M_;
    float* p1 = g_pacc + ((size_t)(r0 + 8) * NSPL + blockIdx.x) * M_;
    int cb = (l & 3) * 2;
    #pragma unroll
    for (int jj = 0; jj < 8; jj++) {
        *(float2*)(p0 + jj * 8 + cb) = make_float2(acc_o[jj][0], acc_o[jj][1]);
        *(float2*)(p1 + jj * 8 + cb) = make_float2(acc_o[jj][2], acc_o[jj][3]);
    }
}

// ---------------- K8: combine partials -> out[:, 256:512] ----------------
__global__ void k_combine(float* __restrict__ out) {
    int q = blockIdx.x;          // r*B + b
    int m = threadIdx.x;         // 64
    float acc = 0.0f, den = 0.0f;
    #pragma unroll
    for (int s = 0; s < NSPL; s++) {
        acc += g_pacc[((size_t)q * NSPL + s) * M_ + m];
        den += g_pden[q * NSPL + s];
    }
    int r = q >> 8, b = q & 255;
    out[b * 512 + 256 + r * M_ + m] = acc / den;
}

// ---------------- launch ----------------
extern "C" void kernel_launch(void* const* d_in, const int* in_sizes, int n_in,
                              void* d_out, int out_size) {
    const float* x    = (const float*)d_in[0];
    const float* A    = (const float*)d_in[1];
    const float* wrp  = (const float*)d_in[2];
    const float* wu   = (const float*)d_in[3];
    const float* rp   = (const float*)d_in[4];
    const float* h    = (const float*)d_in[5];
    const float* c    = (const float*)d_in[6];
    const float* W    = (const float*)d_in[7];
    const float* Uw   = (const float*)d_in[8];
    const float* bias = (const float*)d_in[9];
    const float* Wk   = (const float*)d_in[10];
    const float* bk   = (const float*)d_in[11];
    const float* Wa   = (const float*)d_in[12];
    const float* ba   = (const float*)d_in[13];
    float* out = (float*)d_out;

    k_gates_mma<<<dim3(8, 2, KSPL), 256>>>(x, rp, h, W, Uw);      // 0
    k_lstm_kt  <<<B_, 256>>>(c, out, Wa, ba, Wk, bk, bias);       // 1
    k_dA       <<<dim3(N_ / 128, R_), 256>>>(wrp);                // 2
    k_argmin_a <<<dim3(B_, 4), 256>>>(wu);                        // 3 <- profiled slot
    k_argmin_b <<<1, 256>>>();                                    // 4
    k_scatter  <<<dim3(B_, R_), 256>>>();                         // 5
    k_chain    <<<N_ / 64, 256>>>(A);                             // 6
    k_read     <<<dim3(NSPL, 8), 256>>>();                        // 7
    k_combine  <<<QT_, 64>>>(out);                                // 8
}